// round 12
// baseline (speedup 1.0000x reference)
#include <cuda_runtime.h>
#include <cuda_bf16.h>
#include <mma.h>

using namespace nvcuda;

#define Nn 100000
#define Rr 6
#define Ee 400000
#define Ff 128
#define RE (Rr*Ee)        // 2,400,000 edges total
#define NR (Nn*Rr)        // 600,000 (dst,rel) rows
#define SEG 32            // fixed entries per row segment (P(overflow) ~ 1e-13)
#define MBLK 128
#define NBLKS ((Nn + MBLK - 1) / MBLK)   // 782
#define NTHR 512

// ---------------- scratch (__device__ globals; no runtime alloc) -------------
__device__ int   g_cntout[NR];                 // out-degree per (r,src)
__device__ int   g_counts[NR];                 // in-degree per row (dst*Rr+r)
__device__ int   g_cursor[NR];                 // scatter cursors (init rid*SEG)
__device__ uint2 g_ent[(size_t)NR*SEG];        // (src, ns bits) fixed segments (153.6MB)
__device__ __nv_bfloat16 g_xb[Nn*Ff];          // bf16 x (25.6 MB, L2-resident)
__device__ __nv_bfloat16 g_Whi[Rr*Ff*Ff];      // bf16 W1 high part
__device__ __nv_bfloat16 g_Wlo[Rr*Ff*Ff];      // bf16 W1 residual
__device__ float g_b1sum[Ff];                  // sum_r b1[r]
__device__ float g_csum[NR];                   // per (r,src): sum of nd[dst] over out-edges
__device__ float g_M[Rr*Ff];                   // M[r] = sum_n wc_r[n] * relu(h1[n])

// ---------------- setup -------------------------------------------------------
// zeros + cursor init + x->bf16 + W1 hi/lo split + b1 sum
__global__ void k_init(const float* __restrict__ x,
                       const float* __restrict__ W1, const float* __restrict__ b1) {
    int i = blockIdx.x * blockDim.x + threadIdx.x;
    if (i < NR) {
        g_cntout[i] = 0; g_counts[i] = 0; g_csum[i] = 0.f;
        g_cursor[i] = i * SEG;
    }
    if (i < Nn*Ff) g_xb[i] = __float2bfloat16(x[i]);
    if (i < Rr*Ff*Ff) {
        float w = W1[i];
        __nv_bfloat16 hi = __float2bfloat16(w);
        g_Whi[i] = hi;
        g_Wlo[i] = __float2bfloat16(w - __bfloat162float(hi));
    }
    if (i < Ff) {
        float s = 0.f;
        for (int r = 0; r < Rr; r++) s += b1[r*Ff + i];
        g_b1sum[i] = s;
    }
    if (i < Rr*Ff) g_M[i] = 0.f;
}

__global__ void k_deg(const int* __restrict__ src, const int* __restrict__ dst) {
    int i = blockIdx.x * blockDim.x + threadIdx.x;
    if (i >= RE) return;
    int r = i / Ee;
    atomicAdd(&g_cntout[r*Nn + src[i]], 1);
    atomicAdd(&g_counts[dst[i]*Rr + r], 1);
}

// scatter (src, ns[src]) into fixed segments + layer-2 coefficient sums.
// norms computed per-edge from counts (both counts > 0 since this edge exists).
__global__ void k_scatter(const int* __restrict__ src, const int* __restrict__ dst) {
    int i = blockIdx.x * blockDim.x + threadIdx.x;
    if (i >= RE) return;
    int r = i / Ee;
    int s = src[i], d = dst[i];
    int rid = d*Rr + r;
    int pos = atomicAdd(&g_cursor[rid], 1);
    float ns = rsqrtf((float)g_cntout[r*Nn + s]);
    g_ent[pos] = make_uint2((unsigned)s, __float_as_uint(ns));
    float nd = rsqrtf((float)g_counts[rid]);
    atomicAdd(&g_csum[r*Nn + s], nd);
}

// ---------------- fused aggregate + GEMM + M-reduction ------------------------
// 512 threads / 16 warps, 2 blocks/SM. Per 128-dst tile: per relation,
// 16 warps aggregate 8 rows each into smem bf16 (fixed segments: off=rid*SEG,
// only counts loaded), then MMA vs Whi/Wlo direct from global. Epilogue:
// relu+bias, weights from cntout/csum, weighted reduction into g_M.
__global__ void __launch_bounds__(NTHR, 2) k_fused() {
    __shared__ __align__(16) char sm[48128];
    __nv_bfloat16* Ag = reinterpret_cast<__nv_bfloat16*>(sm);          // 128x128 (32KB)
    int t = threadIdx.x, warp = t >> 5, lane = t & 31;
    int wm = warp >> 2, wn = warp & 3;          // 4 x 4 warp grid, each 32x32 of C
    int rowbase = blockIdx.x * MBLK;

    wmma::fragment<wmma::accumulator, 16, 16, 16, float> acc[2][2];
    #pragma unroll
    for (int i = 0; i < 2; i++)
        #pragma unroll
        for (int j = 0; j < 2; j++) wmma::fill_fragment(acc[i][j], 0.f);

    for (int r = 0; r < Rr; r++) {
        // ---- aggregate: 8 rows per warp, count pipelined one row ahead ----
        int rowi = warp;
        int cnt_c = 0;
        {
            int dst = rowbase + rowi;
            if (dst < Nn) cnt_c = g_counts[dst*Rr + r];
        }
        #pragma unroll
        for (int it = 0; it < 8; it++) {
            int rowi_n = rowi + 16;
            int cnt_n = 0;
            if (it < 7) {
                int dstn = rowbase + rowi_n;
                if (dstn < Nn) cnt_n = g_counts[dstn*Rr + r];
            }
            int dst = rowbase + rowi;
            int off_c = (dst*Rr + r) * SEG;           // fixed segment, no load
            float4 a = make_float4(0.f, 0.f, 0.f, 0.f);
            {
                const uint2* ep = g_ent + off_c;
                int k = 0;
                for (; k + 4 <= cnt_c; k += 4) {      // 4 gathers in flight
                    uint2 e0 = ep[k+0], e1 = ep[k+1], e2 = ep[k+2], e3 = ep[k+3];
                    uint2 u0 = reinterpret_cast<const uint2*>(g_xb + e0.x*Ff)[lane];
                    uint2 u1 = reinterpret_cast<const uint2*>(g_xb + e1.x*Ff)[lane];
                    uint2 u2 = reinterpret_cast<const uint2*>(g_xb + e2.x*Ff)[lane];
                    uint2 u3 = reinterpret_cast<const uint2*>(g_xb + e3.x*Ff)[lane];
                    float w0 = __uint_as_float(e0.y), w1 = __uint_as_float(e1.y);
                    float w2 = __uint_as_float(e2.y), w3 = __uint_as_float(e3.y);
                    float2 p0 = __bfloat1622float2(*reinterpret_cast<__nv_bfloat162*>(&u0.x));
                    float2 q0 = __bfloat1622float2(*reinterpret_cast<__nv_bfloat162*>(&u0.y));
                    float2 p1 = __bfloat1622float2(*reinterpret_cast<__nv_bfloat162*>(&u1.x));
                    float2 q1 = __bfloat1622float2(*reinterpret_cast<__nv_bfloat162*>(&u1.y));
                    float2 p2 = __bfloat1622float2(*reinterpret_cast<__nv_bfloat162*>(&u2.x));
                    float2 q2 = __bfloat1622float2(*reinterpret_cast<__nv_bfloat162*>(&u2.y));
                    float2 p3 = __bfloat1622float2(*reinterpret_cast<__nv_bfloat162*>(&u3.x));
                    float2 q3 = __bfloat1622float2(*reinterpret_cast<__nv_bfloat162*>(&u3.y));
                    a.x += w0*p0.x + w1*p1.x + w2*p2.x + w3*p3.x;
                    a.y += w0*p0.y + w1*p1.y + w2*p2.y + w3*p3.y;
                    a.z += w0*q0.x + w1*q1.x + w2*q2.x + w3*q3.x;
                    a.w += w0*q0.y + w1*q1.y + w2*q2.y + w3*q3.y;
                }
                for (; k < cnt_c; k++) {
                    uint2 e0 = ep[k];
                    uint2 u0 = reinterpret_cast<const uint2*>(g_xb + e0.x*Ff)[lane];
                    float w0 = __uint_as_float(e0.y);
                    float2 p0 = __bfloat1622float2(*reinterpret_cast<__nv_bfloat162*>(&u0.x));
                    float2 q0 = __bfloat1622float2(*reinterpret_cast<__nv_bfloat162*>(&u0.y));
                    a.x += w0*p0.x;  a.y += w0*p0.y;
                    a.z += w0*q0.x;  a.w += w0*q0.y;
                }
            }
            float nd = (cnt_c > 0) ? rsqrtf((float)cnt_c) : 0.f;
            a.x *= nd; a.y *= nd; a.z *= nd; a.w *= nd;
            __nv_bfloat162 o0 = __floats2bfloat162_rn(a.x, a.y);
            __nv_bfloat162 o1 = __floats2bfloat162_rn(a.z, a.w);
            uint2 ou;
            ou.x = *reinterpret_cast<unsigned*>(&o0);
            ou.y = *reinterpret_cast<unsigned*>(&o1);
            reinterpret_cast<uint2*>(Ag + rowi*Ff)[lane] = ou;
            rowi = rowi_n; cnt_c = cnt_n;
        }
        __syncthreads();                      // Ag complete

        // ---- MMA: C += Ag @ (Whi_r + Wlo_r); B direct from global ----
        const __nv_bfloat16* Wh = g_Whi + r*Ff*Ff;
        const __nv_bfloat16* Wl = g_Wlo + r*Ff*Ff;
        #pragma unroll
        for (int kf = 0; kf < Ff; kf += 16) {
            #pragma unroll
            for (int i = 0; i < 2; i++) {
                wmma::fragment<wmma::matrix_a, 16, 16, 16, __nv_bfloat16, wmma::row_major> af;
                wmma::load_matrix_sync(af, Ag + (wm*32 + i*16)*Ff + kf, Ff);
                #pragma unroll
                for (int j = 0; j < 2; j++) {
                    wmma::fragment<wmma::matrix_b, 16, 16, 16, __nv_bfloat16, wmma::row_major> bf;
                    wmma::load_matrix_sync(bf, Wh + kf*Ff + wn*32 + j*16, Ff);
                    wmma::mma_sync(acc[i][j], af, bf, acc[i][j]);
                    wmma::load_matrix_sync(bf, Wl + kf*Ff + wn*32 + j*16, Ff);
                    wmma::mma_sync(acc[i][j], af, bf, acc[i][j]);
                }
            }
        }
        __syncthreads();                      // MMA reads done before Ag overwrite
    }

    // ---- fused epilogue: relu + bias, weighted reduction into g_M ----
    float* Cs = reinterpret_cast<float*>(sm);                // 64x128 f32 (32KB)
    float* wc = reinterpret_cast<float*>(sm + 32768);        // [6][128]  (3KB)
    float* Mp = reinterpret_cast<float*>(sm + 35840);        // [4][6][128] (12KB)

    int col = t & 127;
    int q   = t >> 7;                        // thread quarter 0..3
    float b1s = g_b1sum[col];
    float ma[Rr];
    #pragma unroll
    for (int r = 0; r < Rr; r++) ma[r] = 0.f;

    for (int u = t; u < Rr*MBLK; u += NTHR) {
        int r = u >> 7, row = u & 127;
        int gr = rowbase + row;
        float v = 0.f;
        if (gr < Nn) {
            int co = g_cntout[r*Nn + gr];
            if (co > 0) v = rsqrtf((float)co) * g_csum[r*Nn + gr];
        }
        wc[u] = v;
    }

    #pragma unroll
    for (int p = 0; p < 2; p++) {
        __syncthreads();                     // smem free / prev pass consumed
        if ((wm >> 1) == p) {                // warps owning rows [p*64, p*64+64)
            #pragma unroll
            for (int i = 0; i < 2; i++)
                #pragma unroll
                for (int j = 0; j < 2; j++)
                    wmma::store_matrix_sync(Cs + ((wm & 1)*32 + i*16)*128 + wn*32 + j*16,
                                            acc[i][j], 128, wmma::mem_row_major);
        }
        __syncthreads();
        #pragma unroll 4
        for (int rw = 0; rw < 16; rw++) {
            int row64 = q*16 + rw;
            int grow  = p*64 + row64;
            float v = fmaxf(Cs[row64*128 + col] + b1s, 0.f);   // h1 (fp32)
            #pragma unroll
            for (int r = 0; r < Rr; r++)
                ma[r] += wc[r*MBLK + grow] * v;
        }
    }
    __syncthreads();
    #pragma unroll
    for (int r = 0; r < Rr; r++) Mp[(q*Rr + r)*128 + col] = ma[r];
    __syncthreads();
    for (int u = t; u < Rr*Ff; u += NTHR)
        atomicAdd(&g_M[u], Mp[u] + Mp[768 + u] + Mp[1536 + u] + Mp[2304 + u]);
}

// g = (1/N) sum_r M[r] @ W2_r + sum_r b2_r ; out = g @ Wc + bc
__global__ void k_out(const float* __restrict__ W2, const float* __restrict__ b2,
                      const float* __restrict__ Wc, const float* __restrict__ bc,
                      float* __restrict__ out) {
    __shared__ float g[Ff];
    int t = threadIdx.x;
    float acc = 0.f, bb = 0.f;
    for (int r = 0; r < Rr; r++) {
        const float* W2r = W2 + r*Ff*Ff;
        for (int h = 0; h < Ff; h++)
            acc += g_M[r*Ff + h] * W2r[h*Ff + t];
        bb += b2[r*Ff + t];
    }
    g[t] = acc * (1.f / (float)Nn) + bb;
    __syncthreads();
    if (t < 2) {
        float o = bc[t];
        for (int h = 0; h < Ff; h++) o += g[h] * Wc[h*2 + t];
        out[t] = o;
    }
}

// ---------------- launch ------------------------------------------------------
extern "C" void kernel_launch(void* const* d_in, const int* in_sizes, int n_in,
                              void* d_out, int out_size) {
    const float* x    = (const float*)d_in[0];
    const int*   esrc = (const int*)  d_in[1];
    const int*   edst = (const int*)  d_in[2];
    const float* W1   = (const float*)d_in[3];
    const float* b1   = (const float*)d_in[4];
    const float* W2   = (const float*)d_in[5];
    const float* b2   = (const float*)d_in[6];
    const float* Wc   = (const float*)d_in[7];
    const float* bc   = (const float*)d_in[8];
    float* out = (float*)d_out;

    k_init   <<<(Nn*Ff + 255)/256, 256>>>(x, W1, b1);   // launch 1
    k_deg    <<<(RE + 255)/256, 256>>>(esrc, edst);     // launch 2
    k_scatter<<<(RE + 255)/256, 256>>>(esrc, edst);     // launch 3
    k_fused  <<<NBLKS, NTHR>>>();                       // launch 4  (ncu window)
    k_out    <<<1, 128>>>(W2, b2, Wc, bc, out);         // launch 5
}